// round 2
// baseline (speedup 1.0000x reference)
#include <cuda_runtime.h>

#define N_NODES 100000
#define N_EDGES 1600000
#define DIM 128
#define NLAYER 5

// ---------------- scratch (device globals; no allocations) ----------------
__device__ float g_h[N_NODES * DIM];          // current node features
__device__ float g_agg[N_NODES * DIM];        // aggregated messages
__device__ float g_mid[N_NODES * 2 * DIM];    // MLP hidden
__device__ int   g_rowptr[N_NODES + 1];
__device__ int   g_cursor[N_NODES];
__device__ int   g_cnt[N_NODES];
__device__ int   g_edge[N_EDGES];             // packed: src | eb<<20 | ed<<24

// ---------------- CSR build ----------------
__global__ void k_zero_cnt(int n) {
    int i = blockIdx.x * blockDim.x + threadIdx.x;
    if (i < n) g_cnt[i] = 0;
}

__global__ void k_count(const int* __restrict__ dst, int E) {
    int e = blockIdx.x * blockDim.x + threadIdx.x;
    if (e < E) atomicAdd(&g_cnt[dst[e]], 1);
}

// single-block exclusive scan over g_cnt -> g_rowptr, g_cursor
__global__ void k_scan(int n) {
    __shared__ int wsum[32];
    __shared__ int carry_s;
    if (threadIdx.x == 0) carry_s = 0;
    __syncthreads();
    int lane = threadIdx.x & 31, wid = threadIdx.x >> 5;
    for (int base = 0; base < n; base += 1024) {
        int i = base + threadIdx.x;
        int v = (i < n) ? g_cnt[i] : 0;
        int s = v;
        #pragma unroll
        for (int o = 1; o < 32; o <<= 1) {
            int t = __shfl_up_sync(0xffffffffu, s, o);
            if (lane >= o) s += t;
        }
        if (lane == 31) wsum[wid] = s;
        __syncthreads();
        if (wid == 0) {
            int ws = wsum[lane];
            #pragma unroll
            for (int o = 1; o < 32; o <<= 1) {
                int t = __shfl_up_sync(0xffffffffu, ws, o);
                if (lane >= o) ws += t;
            }
            wsum[lane] = ws;
        }
        __syncthreads();
        int excl = s - v + (wid ? wsum[wid - 1] : 0) + carry_s;
        if (i < n) { g_rowptr[i] = excl; g_cursor[i] = excl; }
        __syncthreads();
        if (threadIdx.x == 1023) carry_s = excl + v;
        __syncthreads();
    }
    if (threadIdx.x == 0) g_rowptr[n] = carry_s;
}

__global__ void k_fill(const int* __restrict__ src, const int* __restrict__ dst,
                       const int* __restrict__ eattr, int E) {
    int e = blockIdx.x * blockDim.x + threadIdx.x;
    if (e >= E) return;
    int d = dst[e];
    int pos = atomicAdd(&g_cursor[d], 1);
    int eb = eattr[2 * e];
    int ed = eattr[2 * e + 1];
    g_edge[pos] = src[e] | (eb << 20) | (ed << 24);
}

// ---------------- node input embedding ----------------
__global__ void k_embed(const int* __restrict__ x, const float* __restrict__ xemb, int n) {
    int i = blockIdx.x * blockDim.x + threadIdx.x;
    int v = i >> 5, c = (i & 31) * 4;
    if (v >= n) return;
    int a = x[2 * v], ch = x[2 * v + 1];
    float4 va = *(const float4*)(xemb + (size_t)a * DIM + c);
    float4 vb = *(const float4*)(xemb + (size_t)(120 + ch) * DIM + c);
    float4 r;
    r.x = va.x + vb.x; r.y = va.y + vb.y; r.z = va.z + vb.z; r.w = va.w + vb.w;
    *(float4*)(g_h + (size_t)v * DIM + c) = r;
}

// ---------------- aggregation: one warp per node ----------------
__global__ void k_agg(const float* __restrict__ etab_l, int n) {
    __shared__ float4 etb[9 * 32];   // etab for this layer, as float4 per lane
    for (int i = threadIdx.x; i < 9 * 32; i += blockDim.x)
        etb[i] = ((const float4*)etab_l)[i];
    __syncthreads();
    int w = (blockIdx.x * blockDim.x + threadIdx.x) >> 5;
    int lane = threadIdx.x & 31;
    if (w >= n) return;
    int beg = g_rowptr[w], end = g_rowptr[w + 1];
    float4 acc = *(const float4*)(g_h + (size_t)w * DIM + lane * 4);
    // self-loop: bond=4 (row 4), direction=0 (row 6)
    float4 sl = etb[4 * 32 + lane];
    float4 sd = etb[6 * 32 + lane];
    acc.x += sl.x + sd.x; acc.y += sl.y + sd.y;
    acc.z += sl.z + sd.z; acc.w += sl.w + sd.w;
    for (int p = beg; p < end; p++) {
        int pk = g_edge[p];
        int s  = pk & 0xFFFFF;
        float4 hv = *(const float4*)(g_h + (size_t)s * DIM + lane * 4);
        float4 b4 = etb[((pk >> 20) & 3) * 32 + lane];
        float4 d4 = etb[(6 + ((pk >> 24) & 3)) * 32 + lane];
        acc.x += hv.x + b4.x + d4.x;
        acc.y += hv.y + b4.y + d4.y;
        acc.z += hv.z + b4.z + d4.z;
        acc.w += hv.w + b4.w + d4.w;
    }
    *(float4*)(g_agg + (size_t)w * DIM + lane * 4) = acc;
}

// ---------------- GEMM: C[M,JTOT] = A[M,K] @ W[JTOT,K]^T, fused epilogue ----------------
__device__ __forceinline__ void ffma2(unsigned long long& d, unsigned long long a,
                                      unsigned long long b) {
    asm("fma.rn.f32x2 %0, %1, %2, %0;" : "+l"(d) : "l"(a), "l"(b));
}

#define AS_STRIDE 132
#define BS_STRIDE 260
#define GEMM_SMEM ((64 * AS_STRIDE + 64 * BS_STRIDE) * 4)

template <int K, int JTOT, bool BN, bool RELU>
__launch_bounds__(256, 2)
__global__ void k_gemm(const float* __restrict__ A, const float* __restrict__ W,
                       const float* __restrict__ bias,
                       const float* __restrict__ gamma, const float* __restrict__ beta,
                       const float* __restrict__ mean, const float* __restrict__ var,
                       float* __restrict__ C, int M) {
    extern __shared__ float sm[];
    float* As = sm;                      // [64][AS_STRIDE] k-major
    float* Bs = sm + 64 * AS_STRIDE;     // [64][BS_STRIDE] pair-duplicated
    int tid = threadIdx.x;
    int tc = tid & 15, tr = tid >> 4;
    int mb = blockIdx.x, jbase = blockIdx.y * 128;

    unsigned long long acc[32];
    #pragma unroll
    for (int i = 0; i < 32; i++) acc[i] = 0ull;

    for (int kb = 0; kb < K; kb += 64) {
        // stage A tile (128 rows x 64 k) transposed to k-major
        #pragma unroll
        for (int t = 0; t < 8; t++) {
            int idx = tid + t * 256;
            int row = idx >> 4, kq = idx & 15;
            int rg = mb * 128 + row;
            float4 a = (rg < M) ? *(const float4*)(A + (size_t)rg * K + kb + kq * 4)
                                : make_float4(0.f, 0.f, 0.f, 0.f);
            float* p = As + (kq * 4) * AS_STRIDE + row;
            p[0] = a.x; p[AS_STRIDE] = a.y; p[2 * AS_STRIDE] = a.z; p[3 * AS_STRIDE] = a.w;
        }
        // stage W tile (128 cols x 64 k) pair-duplicated, k-major
        #pragma unroll
        for (int t = 0; t < 8; t++) {
            int idx = tid + t * 256;
            int jr = idx >> 4, kq = idx & 15;
            float4 wv = *(const float4*)(W + (size_t)(jbase + jr) * K + kb + kq * 4);
            float* p = Bs + (kq * 4) * BS_STRIDE + 2 * jr;
            p[0] = wv.x;                  p[1] = wv.x;
            p[BS_STRIDE] = wv.y;          p[BS_STRIDE + 1] = wv.y;
            p[2 * BS_STRIDE] = wv.z;      p[2 * BS_STRIDE + 1] = wv.z;
            p[3 * BS_STRIDE] = wv.w;      p[3 * BS_STRIDE + 1] = wv.w;
        }
        __syncthreads();
        #pragma unroll 8
        for (int k = 0; k < 64; k++) {
            const unsigned long long* ap =
                (const unsigned long long*)(As + k * AS_STRIDE + tr * 8);
            const unsigned long long* bp =
                (const unsigned long long*)(Bs + k * BS_STRIDE + tc * 16);
            unsigned long long a0 = ap[0], a1 = ap[1], a2 = ap[2], a3 = ap[3];
            unsigned long long b0 = bp[0], b1 = bp[1], b2 = bp[2], b3 = bp[3];
            unsigned long long b4 = bp[4], b5 = bp[5], b6 = bp[6], b7 = bp[7];
            ffma2(acc[0],  a0, b0); ffma2(acc[1],  a0, b1);
            ffma2(acc[2],  a0, b2); ffma2(acc[3],  a0, b3);
            ffma2(acc[4],  a0, b4); ffma2(acc[5],  a0, b5);
            ffma2(acc[6],  a0, b6); ffma2(acc[7],  a0, b7);
            ffma2(acc[8],  a1, b0); ffma2(acc[9],  a1, b1);
            ffma2(acc[10], a1, b2); ffma2(acc[11], a1, b3);
            ffma2(acc[12], a1, b4); ffma2(acc[13], a1, b5);
            ffma2(acc[14], a1, b6); ffma2(acc[15], a1, b7);
            ffma2(acc[16], a2, b0); ffma2(acc[17], a2, b1);
            ffma2(acc[18], a2, b2); ffma2(acc[19], a2, b3);
            ffma2(acc[20], a2, b4); ffma2(acc[21], a2, b5);
            ffma2(acc[22], a2, b6); ffma2(acc[23], a2, b7);
            ffma2(acc[24], a3, b0); ffma2(acc[25], a3, b1);
            ffma2(acc[26], a3, b2); ffma2(acc[27], a3, b3);
            ffma2(acc[28], a3, b4); ffma2(acc[29], a3, b5);
            ffma2(acc[30], a3, b6); ffma2(acc[31], a3, b7);
        }
        __syncthreads();
    }

    // fused epilogue: bias (+ BN) (+ ReLU)
    float cs[8], csh[8];
    #pragma unroll
    for (int c = 0; c < 8; c++) {
        int j = jbase + tc * 8 + c;
        if (BN) {
            float s = gamma[j] * rsqrtf(var[j] + 1e-5f);
            cs[c] = s;
            csh[c] = (bias[j] - mean[j]) * s + beta[j];
        } else {
            cs[c] = 1.f;
            csh[c] = bias[j];
        }
    }
    #pragma unroll
    for (int rp = 0; rp < 4; rp++) {
        #pragma unroll
        for (int h = 0; h < 2; h++) {
            int row = mb * 128 + tr * 8 + rp * 2 + h;
            if (row < M) {
                float o[8];
                #pragma unroll
                for (int c = 0; c < 8; c++) {
                    unsigned long long u = acc[rp * 8 + c];
                    unsigned int bits = h ? (unsigned int)(u >> 32) : (unsigned int)u;
                    float v = __uint_as_float(bits);
                    v = v * cs[c] + csh[c];
                    if (RELU) v = fmaxf(v, 0.f);
                    o[c] = v;
                }
                float4* outp = (float4*)(C + (size_t)row * JTOT + jbase + tc * 8);
                outp[0] = make_float4(o[0], o[1], o[2], o[3]);
                outp[1] = make_float4(o[4], o[5], o[6], o[7]);
            }
        }
    }
}

// ---------------- launch ----------------
extern "C" void kernel_launch(void* const* d_in, const int* in_sizes, int n_in,
                              void* d_out, int out_size) {
    const int*   x     = (const int*)d_in[0];
    const int*   eidx  = (const int*)d_in[1];
    const int*   eattr = (const int*)d_in[2];
    const float* xemb  = (const float*)d_in[3];
    const float* etab  = (const float*)d_in[4];
    const float* w1    = (const float*)d_in[5];
    const float* b1    = (const float*)d_in[6];
    const float* w2    = (const float*)d_in[7];
    const float* b2    = (const float*)d_in[8];
    const float* gamma = (const float*)d_in[9];
    const float* beta  = (const float*)d_in[10];
    const float* bnm   = (const float*)d_in[11];
    const float* bnv   = (const float*)d_in[12];
    float* out = (float*)d_out;

    int n = in_sizes[0] / 2;
    int E = in_sizes[1] / 2;
    const int* srcp = eidx;
    const int* dstp = eidx + E;

    cudaFuncSetAttribute(k_gemm<128, 256, false, true>,
                         cudaFuncAttributeMaxDynamicSharedMemorySize, GEMM_SMEM);
    cudaFuncSetAttribute(k_gemm<256, 128, true, true>,
                         cudaFuncAttributeMaxDynamicSharedMemorySize, GEMM_SMEM);
    cudaFuncSetAttribute(k_gemm<256, 128, true, false>,
                         cudaFuncAttributeMaxDynamicSharedMemorySize, GEMM_SMEM);

    void *ph, *pagg, *pmid;
    cudaGetSymbolAddress(&ph, g_h);
    cudaGetSymbolAddress(&pagg, g_agg);
    cudaGetSymbolAddress(&pmid, g_mid);
    float* H = (float*)ph;
    float* AG = (float*)pagg;
    float* MID = (float*)pmid;

    // CSR build (runs every replay; deterministic up to fp summation order)
    k_zero_cnt<<<(n + 255) / 256, 256>>>(n);
    k_count<<<(E + 255) / 256, 256>>>(dstp, E);
    k_scan<<<1, 1024>>>(n);
    k_fill<<<(E + 255) / 256, 256>>>(srcp, dstp, eattr, E);
    k_embed<<<(n * 32 + 255) / 256, 256>>>(x, xemb, n);

    int mblocks = (n + 127) / 128;
    for (int l = 0; l < NLAYER; l++) {
        k_agg<<<(n * 32 + 255) / 256, 256>>>(etab + (size_t)l * 9 * DIM, n);
        // GEMM1: [n,128] x [256,128]^T -> g_mid [n,256], +bias, ReLU
        k_gemm<128, 256, false, true><<<dim3(mblocks, 2), 256, GEMM_SMEM>>>(
            AG, w1 + (size_t)l * 2 * DIM * DIM, b1 + (size_t)l * 2 * DIM,
            nullptr, nullptr, nullptr, nullptr, MID, n);
        // GEMM2: [n,256] x [128,256]^T -> h (or out), +bias, BN, ReLU (except last)
        const float* g = gamma + (size_t)l * DIM;
        const float* bt = beta + (size_t)l * DIM;
        const float* mn = bnm + (size_t)l * DIM;
        const float* vr = bnv + (size_t)l * DIM;
        const float* W2 = w2 + (size_t)l * DIM * 2 * DIM;
        const float* B2 = b2 + (size_t)l * DIM;
        if (l < NLAYER - 1) {
            k_gemm<256, 128, true, true><<<dim3(mblocks, 1), 256, GEMM_SMEM>>>(
                MID, W2, B2, g, bt, mn, vr, H, n);
        } else {
            k_gemm<256, 128, true, false><<<dim3(mblocks, 1), 256, GEMM_SMEM>>>(
                MID, W2, B2, g, bt, mn, vr, out, n);
        }
    }
}

// round 3
// speedup vs baseline: 1.7941x; 1.7941x over previous
#include <cuda_runtime.h>

#define N_NODES 100000
#define N_EDGES 1600000
#define DIM 128
#define NLAYER 5

// ---------------- scratch (device globals; no allocations) ----------------
__device__ float g_h[N_NODES * DIM];          // current node features
__device__ float g_agg[N_NODES * DIM];        // aggregated messages
__device__ float g_mid[N_NODES * 2 * DIM];    // MLP hidden
__device__ int   g_rowptr[N_NODES + 1];
__device__ int   g_cursor[N_NODES];
__device__ int   g_cnt[N_NODES];
__device__ int   g_edge[N_EDGES];             // packed: src | combined_idx<<20

// ---------------- CSR build ----------------
__global__ void k_zero_cnt(int n) {
    int i = blockIdx.x * blockDim.x + threadIdx.x;
    if (i < n) g_cnt[i] = 0;
}

__global__ void k_count(const int* __restrict__ dst, int E) {
    int e = blockIdx.x * blockDim.x + threadIdx.x;
    if (e < E) atomicAdd(&g_cnt[dst[e]], 1);
}

// single-block exclusive scan over g_cnt -> g_rowptr, g_cursor
__global__ void k_scan(int n) {
    __shared__ int wsum[32];
    __shared__ int carry_s;
    if (threadIdx.x == 0) carry_s = 0;
    __syncthreads();
    int lane = threadIdx.x & 31, wid = threadIdx.x >> 5;
    for (int base = 0; base < n; base += 1024) {
        int i = base + threadIdx.x;
        int v = (i < n) ? g_cnt[i] : 0;
        int s = v;
        #pragma unroll
        for (int o = 1; o < 32; o <<= 1) {
            int t = __shfl_up_sync(0xffffffffu, s, o);
            if (lane >= o) s += t;
        }
        if (lane == 31) wsum[wid] = s;
        __syncthreads();
        if (wid == 0) {
            int ws = wsum[lane];
            #pragma unroll
            for (int o = 1; o < 32; o <<= 1) {
                int t = __shfl_up_sync(0xffffffffu, ws, o);
                if (lane >= o) ws += t;
            }
            wsum[lane] = ws;
        }
        __syncthreads();
        int excl = s - v + (wid ? wsum[wid - 1] : 0) + carry_s;
        if (i < n) { g_rowptr[i] = excl; g_cursor[i] = excl; }
        __syncthreads();
        if (threadIdx.x == 1023) carry_s = excl + v;
        __syncthreads();
    }
    if (threadIdx.x == 0) g_rowptr[n] = carry_s;
}

__global__ void k_fill(const int* __restrict__ src, const int* __restrict__ dst,
                       const int* __restrict__ eattr, int E) {
    int e = blockIdx.x * blockDim.x + threadIdx.x;
    if (e >= E) return;
    int d = dst[e];
    int pos = atomicAdd(&g_cursor[d], 1);
    int eb = eattr[2 * e];
    int ed = eattr[2 * e + 1];
    int ci = eb * 3 + ed;                 // combined table index (bond, dir)
    g_edge[pos] = src[e] | (ci << 20);
}

// ---------------- node input embedding ----------------
__global__ void k_embed(const int* __restrict__ x, const float* __restrict__ xemb, int n) {
    int i = blockIdx.x * blockDim.x + threadIdx.x;
    int v = i >> 5, c = (i & 31) * 4;
    if (v >= n) return;
    int a = x[2 * v], ch = x[2 * v + 1];
    float4 va = *(const float4*)(xemb + (size_t)a * DIM + c);
    float4 vb = *(const float4*)(xemb + (size_t)(120 + ch) * DIM + c);
    float4 r;
    r.x = va.x + vb.x; r.y = va.y + vb.y; r.z = va.z + vb.z; r.w = va.w + vb.w;
    *(float4*)(g_h + (size_t)v * DIM + c) = r;
}

// ---------------- aggregation: one warp per node, combined edge table ----------------
__global__ void k_agg(const float* __restrict__ etab_l, int n) {
    __shared__ float4 ctb[18 * 32];   // combined bond+dir table (eb*3+ed)
    for (int i = threadIdx.x; i < 18 * 32; i += blockDim.x) {
        int comb = i >> 5, ln = i & 31;
        int eb = comb / 3, ed = comb - eb * 3;
        float4 b = ((const float4*)etab_l)[eb * 32 + ln];
        float4 d = ((const float4*)(etab_l + 6 * DIM))[ed * 32 + ln];
        ctb[i] = make_float4(b.x + d.x, b.y + d.y, b.z + d.z, b.w + d.w);
    }
    __syncthreads();
    int w = (blockIdx.x * blockDim.x + threadIdx.x) >> 5;
    int lane = threadIdx.x & 31;
    if (w >= n) return;
    int beg = g_rowptr[w], end = g_rowptr[w + 1];
    float4 acc0 = *(const float4*)(g_h + (size_t)w * DIM + lane * 4);
    // self-loop: bond=4, dir=0 -> combined index 12
    {
        float4 sl = ctb[12 * 32 + lane];
        acc0.x += sl.x; acc0.y += sl.y; acc0.z += sl.z; acc0.w += sl.w;
    }
    float4 acc1 = make_float4(0.f, 0.f, 0.f, 0.f);
    float4 acc2 = make_float4(0.f, 0.f, 0.f, 0.f);
    float4 acc3 = make_float4(0.f, 0.f, 0.f, 0.f);
    int p = beg;
    for (; p + 4 <= end; p += 4) {
        int pk0 = g_edge[p], pk1 = g_edge[p + 1], pk2 = g_edge[p + 2], pk3 = g_edge[p + 3];
        float4 h0 = *(const float4*)(g_h + (size_t)(pk0 & 0xFFFFF) * DIM + lane * 4);
        float4 h1 = *(const float4*)(g_h + (size_t)(pk1 & 0xFFFFF) * DIM + lane * 4);
        float4 h2 = *(const float4*)(g_h + (size_t)(pk2 & 0xFFFFF) * DIM + lane * 4);
        float4 h3 = *(const float4*)(g_h + (size_t)(pk3 & 0xFFFFF) * DIM + lane * 4);
        float4 e0 = ctb[(pk0 >> 20) * 32 + lane];
        float4 e1 = ctb[(pk1 >> 20) * 32 + lane];
        float4 e2 = ctb[(pk2 >> 20) * 32 + lane];
        float4 e3 = ctb[(pk3 >> 20) * 32 + lane];
        acc0.x += h0.x + e0.x; acc0.y += h0.y + e0.y; acc0.z += h0.z + e0.z; acc0.w += h0.w + e0.w;
        acc1.x += h1.x + e1.x; acc1.y += h1.y + e1.y; acc1.z += h1.z + e1.z; acc1.w += h1.w + e1.w;
        acc2.x += h2.x + e2.x; acc2.y += h2.y + e2.y; acc2.z += h2.z + e2.z; acc2.w += h2.w + e2.w;
        acc3.x += h3.x + e3.x; acc3.y += h3.y + e3.y; acc3.z += h3.z + e3.z; acc3.w += h3.w + e3.w;
    }
    for (; p < end; p++) {
        int pk = g_edge[p];
        float4 hv = *(const float4*)(g_h + (size_t)(pk & 0xFFFFF) * DIM + lane * 4);
        float4 ev = ctb[(pk >> 20) * 32 + lane];
        acc0.x += hv.x + ev.x; acc0.y += hv.y + ev.y;
        acc0.z += hv.z + ev.z; acc0.w += hv.w + ev.w;
    }
    acc0.x += acc1.x + acc2.x + acc3.x;
    acc0.y += acc1.y + acc2.y + acc3.y;
    acc0.z += acc1.z + acc2.z + acc3.z;
    acc0.w += acc1.w + acc2.w + acc3.w;
    *(float4*)(g_agg + (size_t)w * DIM + lane * 4) = acc0;
}

// ---------------- GEMM: C[M,JTOT] = A[M,K] @ W[JTOT,K]^T, fused epilogue ----------------
__device__ __forceinline__ void ffma2(unsigned long long& d, unsigned long long a,
                                      unsigned long long b) {
    asm("fma.rn.f32x2 %0, %1, %2, %0;" : "+l"(d) : "l"(a), "l"(b));
}

#define AS_STRIDE 132
#define BS_STRIDE 260
#define GEMM_SMEM ((64 * AS_STRIDE + 64 * BS_STRIDE) * 4)

template <int K, int JTOT, bool BN, bool RELU>
__launch_bounds__(256, 2)
__global__ void k_gemm(const float* __restrict__ A, const float* __restrict__ W,
                       const float* __restrict__ bias,
                       const float* __restrict__ gamma, const float* __restrict__ beta,
                       const float* __restrict__ mean, const float* __restrict__ var,
                       float* __restrict__ C, int M) {
    extern __shared__ float sm[];
    float* As = sm;                      // [64][AS_STRIDE] k-major
    float* Bs = sm + 64 * AS_STRIDE;     // [64][BS_STRIDE] pair-duplicated
    int tid = threadIdx.x;
    int tc = tid & 15, tr = tid >> 4;
    int mb = blockIdx.x, jbase = blockIdx.y * 128;

    unsigned long long acc[32];
    #pragma unroll
    for (int i = 0; i < 32; i++) acc[i] = 0ull;

    for (int kb = 0; kb < K; kb += 64) {
        // stage A tile (128 rows x 64 k) transposed to k-major
        #pragma unroll
        for (int t = 0; t < 8; t++) {
            int idx = tid + t * 256;
            int row = idx >> 4, kq = idx & 15;
            int rg = mb * 128 + row;
            float4 a = (rg < M) ? *(const float4*)(A + (size_t)rg * K + kb + kq * 4)
                                : make_float4(0.f, 0.f, 0.f, 0.f);
            float* p = As + (kq * 4) * AS_STRIDE + row;
            p[0] = a.x; p[AS_STRIDE] = a.y; p[2 * AS_STRIDE] = a.z; p[3 * AS_STRIDE] = a.w;
        }
        // stage W tile (128 cols x 64 k) pair-duplicated, k-major
        #pragma unroll
        for (int t = 0; t < 8; t++) {
            int idx = tid + t * 256;
            int jr = idx >> 4, kq = idx & 15;
            float4 wv = *(const float4*)(W + (size_t)(jbase + jr) * K + kb + kq * 4);
            float* p = Bs + (kq * 4) * BS_STRIDE + 2 * jr;
            p[0] = wv.x;                  p[1] = wv.x;
            p[BS_STRIDE] = wv.y;          p[BS_STRIDE + 1] = wv.y;
            p[2 * BS_STRIDE] = wv.z;      p[2 * BS_STRIDE + 1] = wv.z;
            p[3 * BS_STRIDE] = wv.w;      p[3 * BS_STRIDE + 1] = wv.w;
        }
        __syncthreads();
        #pragma unroll 8
        for (int k = 0; k < 64; k++) {
            const unsigned long long* ap =
                (const unsigned long long*)(As + k * AS_STRIDE + tr * 8);
            // conflict-free B: ull index tc + c*16 -> 16 lanes span one
            // contiguous 128B run per LDS.64 (columns c*16+tc)
            const unsigned long long* bp =
                (const unsigned long long*)(Bs + k * BS_STRIDE) + tc;
            unsigned long long a0 = ap[0], a1 = ap[1], a2 = ap[2], a3 = ap[3];
            unsigned long long b0 = bp[0],      b1 = bp[16],  b2 = bp[32],  b3 = bp[48];
            unsigned long long b4 = bp[64],     b5 = bp[80],  b6 = bp[96],  b7 = bp[112];
            ffma2(acc[0],  a0, b0); ffma2(acc[1],  a0, b1);
            ffma2(acc[2],  a0, b2); ffma2(acc[3],  a0, b3);
            ffma2(acc[4],  a0, b4); ffma2(acc[5],  a0, b5);
            ffma2(acc[6],  a0, b6); ffma2(acc[7],  a0, b7);
            ffma2(acc[8],  a1, b0); ffma2(acc[9],  a1, b1);
            ffma2(acc[10], a1, b2); ffma2(acc[11], a1, b3);
            ffma2(acc[12], a1, b4); ffma2(acc[13], a1, b5);
            ffma2(acc[14], a1, b6); ffma2(acc[15], a1, b7);
            ffma2(acc[16], a2, b0); ffma2(acc[17], a2, b1);
            ffma2(acc[18], a2, b2); ffma2(acc[19], a2, b3);
            ffma2(acc[20], a2, b4); ffma2(acc[21], a2, b5);
            ffma2(acc[22], a2, b6); ffma2(acc[23], a2, b7);
            ffma2(acc[24], a3, b0); ffma2(acc[25], a3, b1);
            ffma2(acc[26], a3, b2); ffma2(acc[27], a3, b3);
            ffma2(acc[28], a3, b4); ffma2(acc[29], a3, b5);
            ffma2(acc[30], a3, b6); ffma2(acc[31], a3, b7);
        }
        __syncthreads();
    }

    // fused epilogue: bias (+ BN) (+ ReLU); thread's columns are jbase + c*16 + tc
    float cs[8], csh[8];
    #pragma unroll
    for (int c = 0; c < 8; c++) {
        int j = jbase + c * 16 + tc;
        if (BN) {
            float s = gamma[j] * rsqrtf(var[j] + 1e-5f);
            cs[c] = s;
            csh[c] = (bias[j] - mean[j]) * s + beta[j];
        } else {
            cs[c] = 1.f;
            csh[c] = bias[j];
        }
    }
    #pragma unroll
    for (int rp = 0; rp < 4; rp++) {
        #pragma unroll
        for (int h = 0; h < 2; h++) {
            int row = mb * 128 + tr * 8 + rp * 2 + h;
            if (row < M) {
                float* outp = C + (size_t)row * JTOT + jbase + tc;
                #pragma unroll
                for (int c = 0; c < 8; c++) {
                    unsigned long long u = acc[rp * 8 + c];
                    unsigned int bits = h ? (unsigned int)(u >> 32) : (unsigned int)u;
                    float v = __uint_as_float(bits);
                    v = v * cs[c] + csh[c];
                    if (RELU) v = fmaxf(v, 0.f);
                    outp[c * 16] = v;
                }
            }
        }
    }
}

// ---------------- launch ----------------
extern "C" void kernel_launch(void* const* d_in, const int* in_sizes, int n_in,
                              void* d_out, int out_size) {
    const int*   x     = (const int*)d_in[0];
    const int*   eidx  = (const int*)d_in[1];
    const int*   eattr = (const int*)d_in[2];
    const float* xemb  = (const float*)d_in[3];
    const float* etab  = (const float*)d_in[4];
    const float* w1    = (const float*)d_in[5];
    const float* b1    = (const float*)d_in[6];
    const float* w2    = (const float*)d_in[7];
    const float* b2    = (const float*)d_in[8];
    const float* gamma = (const float*)d_in[9];
    const float* beta  = (const float*)d_in[10];
    const float* bnm   = (const float*)d_in[11];
    const float* bnv   = (const float*)d_in[12];
    float* out = (float*)d_out;

    int n = in_sizes[0] / 2;
    int E = in_sizes[1] / 2;
    const int* srcp = eidx;
    const int* dstp = eidx + E;

    cudaFuncSetAttribute(k_gemm<128, 256, false, true>,
                         cudaFuncAttributeMaxDynamicSharedMemorySize, GEMM_SMEM);
    cudaFuncSetAttribute(k_gemm<256, 128, true, true>,
                         cudaFuncAttributeMaxDynamicSharedMemorySize, GEMM_SMEM);
    cudaFuncSetAttribute(k_gemm<256, 128, true, false>,
                         cudaFuncAttributeMaxDynamicSharedMemorySize, GEMM_SMEM);

    void *ph, *pagg, *pmid;
    cudaGetSymbolAddress(&ph, g_h);
    cudaGetSymbolAddress(&pagg, g_agg);
    cudaGetSymbolAddress(&pmid, g_mid);
    float* H = (float*)ph;
    float* AG = (float*)pagg;
    float* MID = (float*)pmid;

    // CSR build (runs every replay; deterministic up to fp summation order)
    k_zero_cnt<<<(n + 255) / 256, 256>>>(n);
    k_count<<<(E + 255) / 256, 256>>>(dstp, E);
    k_scan<<<1, 1024>>>(n);
    k_fill<<<(E + 255) / 256, 256>>>(srcp, dstp, eattr, E);
    k_embed<<<(n * 32 + 255) / 256, 256>>>(x, xemb, n);

    int mblocks = (n + 127) / 128;
    for (int l = 0; l < NLAYER; l++) {
        k_agg<<<(n * 32 + 255) / 256, 256>>>(etab + (size_t)l * 9 * DIM, n);
        // GEMM1: [n,128] x [256,128]^T -> g_mid [n,256], +bias, ReLU
        k_gemm<128, 256, false, true><<<dim3(mblocks, 2), 256, GEMM_SMEM>>>(
            AG, w1 + (size_t)l * 2 * DIM * DIM, b1 + (size_t)l * 2 * DIM,
            nullptr, nullptr, nullptr, nullptr, MID, n);
        // GEMM2: [n,256] x [128,256]^T -> h (or out), +bias, BN, ReLU (except last)
        const float* g = gamma + (size_t)l * DIM;
        const float* bt = beta + (size_t)l * DIM;
        const float* mn = bnm + (size_t)l * DIM;
        const float* vr = bnv + (size_t)l * DIM;
        const float* W2 = w2 + (size_t)l * DIM * 2 * DIM;
        const float* B2 = b2 + (size_t)l * DIM;
        if (l < NLAYER - 1) {
            k_gemm<256, 128, true, true><<<dim3(mblocks, 1), 256, GEMM_SMEM>>>(
                MID, W2, B2, g, bt, mn, vr, H, n);
        } else {
            k_gemm<256, 128, true, false><<<dim3(mblocks, 1), 256, GEMM_SMEM>>>(
                MID, W2, B2, g, bt, mn, vr, out, n);
        }
    }
}